// round 9
// baseline (speedup 1.0000x reference)
#include <cuda_runtime.h>

typedef unsigned long long u64;

#define TPB  256
#define RPB  256                          // rows per tile = 1 per thread
#define SROW 28                           // word stride: 16B-aligned, conflict-free
#define STAGE_W (RPB * SROW)              // 7168 words = 28.7KB
#define GRID_MAIN 1024                    // persistent: ~6-7 blocks/SM, grid-stride

// Transposed coefficient tables (i-major) so one LDC.128 covers 4 h-channels.
struct __align__(16) CTabT {
    float4 pdT[48];   // pdT[i*6+q] = 0.1 * P[4q..4q+3][i]
    float4 c0[6];
    float4 pzT[48];   // pe*sp(P) transposed
    float4 a1[6];
    float4 zm[6];     // -dt*v0 quads
    float  flag;
    float  pad[3];
};

__device__   CTabT g_tab;
__constant__ CTabT c_tab;

__device__ __forceinline__ float sp_f(float x) {
    return fmaxf(x, 0.0f) + __logf(1.0f + __expf(-fabsf(x)));
}
__device__ __forceinline__ float sig_f(float x) {
    return 1.0f / (1.0f + __expf(-x));
}
__device__ __forceinline__ u64 fma2(u64 a, u64 b, u64 c) {
    u64 d;
    asm("fma.rn.f32x2 %0, %1, %2, %3;" : "=l"(d) : "l"(a), "l"(b), "l"(c));
    return d;
}
__device__ __forceinline__ u64 f2u(float a, float b) {
    u64 v;
    asm("mov.b64 %0, {%1, %2};" : "=l"(v) : "f"(a), "f"(b));
    return v;
}
__device__ __forceinline__ float2 u2f(u64 v) {
    float2 r;
    asm("mov.b64 {%0, %1}, %2;" : "=f"(r.x), "=f"(r.y) : "l"(v));
    return r;
}
__device__ __forceinline__ u64 lo64(float4 v) { return f2u(v.x, v.y); }
__device__ __forceinline__ u64 hi64(float4 v) { return f2u(v.z, v.w); }

// ---------------------------------------------------------------------------
// Prologue kernel: one block computes all batch-invariant values -> g_tab.
// ---------------------------------------------------------------------------
__global__ void cb_prologue(const float* __restrict__ W,  const float* __restrict__ P,
                            const float* __restrict__ bv, const float* __restrict__ bz,
                            const float* __restrict__ e,  const float* __restrict__ ep,
                            const float* __restrict__ cx, const float* __restrict__ cu,
                            const float* __restrict__ cU, const float* __restrict__ v0,
                            const float* __restrict__ X0, const float* __restrict__ U0)
{
    __shared__ float rS[24], wS[24], pkr[192], pwr[192];
    const int t = threadIdx.x;

    if (t < 24) {
        float v0v = v0[t];
        float rv  = sig_f(v0v);
        rS[t] = rv;
        float zx = 0.001f + 0.099f * sig_f(cx[t]);
        float X  = zx + (1.0f - zx) * X0[t] - U0[t] * X0[t] * rv;   // delta_t=1
        float zu   = 0.001f + 0.099f * sig_f(cu[t]);
        float Ucap = 0.9f * sig_f(cU[t]);
        float U = Ucap * zu + (1.0f - zu) * U0[t] + Ucap * (1.0f - U0[t]) * rv;
        U = fminf(fmaxf(U, Ucap), 1.0f);
        wS[t] = U * X * rv;
        ((float*)g_tab.zm)[t] = -0.1f * v0v;
    }
    if (t == 0) {
        int f = 0;
        #pragma unroll
        for (int j = 0; j < 24; ++j) f |= (v0[j] != 0.0f);
        g_tab.flag = (float)f;
    }
    __syncthreads();

    if (t < 192) {
        const int h = t >> 3;                 // 0..23
        const int i = t & 7;                  // 0..7
        float kr = 0.0f, wur = 0.0f;
        #pragma unroll
        for (int jj = 0; jj < 3; ++jj) {
            int j = i * 3 + jj;
            float Wv = W[h * 24 + j];
            kr  += sp_f(Wv) * rS[j];
            wur += Wv * wS[j];
        }
        pkr[h * 8 + i] = kr;
        pwr[h * 8 + i] = wur;
        float pe = sp_f(ep[0]);
        float Pv = P[h * 8 + i];              // P is (H, IN) row-major
        ((float*)&g_tab.pdT[i * 6 + (h >> 2)])[h & 3] = 0.1f * Pv;
        ((float*)&g_tab.pzT[i * 6 + (h >> 2)])[h & 3] = pe * sp_f(Pv);
    }
    __syncthreads();

    if (t < 24) {
        float kr = 0.0f, wur = 0.0f;
        #pragma unroll
        for (int k = 0; k < 8; ++k) { kr += pkr[t * 8 + k]; wur += pwr[t * 8 + k]; }
        float ke = sp_f(e[0]);
        ((float*)g_tab.a1)[t] = ke * kr + bz[t];
        ((float*)g_tab.c0)[t] = v0[t] + 0.1f * (wur + bv[t]);
    }
}

// ---------------------------------------------------------------------------
// Persistent main kernel: grid-stride over 256-row tiles; next tile's x LDGs
// issued before the current tile's writeout (latency overlap).
// ---------------------------------------------------------------------------
__global__ void __launch_bounds__(TPB, 6)
cb_main(const float* __restrict__ x, float* __restrict__ out, int B, int nTiles)
{
    __shared__ float sm[STAGE_W];
    const int t = threadIdx.x;
    const bool slow = (c_tab.flag != 0.0f);

    // Tile-invariant writeout source offsets (hoisted g/6 math).
    int soff[6];
    #pragma unroll
    for (int k = 0; k < 6; ++k) {
        unsigned g = (unsigned)(k * 256 + t);
        unsigned r = g / 6u;
        unsigned c = g - r * 6u;
        soff[k] = (int)(r * SROW + 4u * c);
    }

    const unsigned totF4 = (unsigned)B * 6u;
    float4* out4 = (float4*)out;

    int tile = blockIdx.x;
    if (tile >= nTiles) return;

    // Preload first tile's x.
    float xf[8];
    {
        const int row = tile * RPB + t;
        #pragma unroll
        for (int i = 0; i < 8; ++i)
            xf[i] = (row < B) ? __ldcs(x + (size_t)i * (size_t)B + row) : 0.0f;
    }

    for (;;) {
        // Pack (x, x): both f32x2 lanes are h-channels of the same row.
        u64 xp[8];
        #pragma unroll
        for (int i = 0; i < 8; ++i) xp[i] = f2u(xf[i], xf[i]);

        #pragma unroll
        for (int q = 0; q < 6; ++q) {           // h-quad 4q .. 4q+3
            const float4 c0q = c_tab.c0[q];
            u64 a01 = lo64(c0q);
            u64 a23 = hi64(c0q);
            #pragma unroll
            for (int i = 0; i < 8; ++i) {
                const float4 p = c_tab.pdT[i * 6 + q];
                a01 = fma2(lo64(p), xp[i], a01);
                a23 = fma2(hi64(p), xp[i], a23);
            }

            if (slow) {
                // General case (v0 != 0): v += sig(a1 + Pz@x) * (-0.1*v0[h]).
                const float4 a1q = c_tab.a1[q];
                u64 z01 = lo64(a1q);
                u64 z23 = hi64(a1q);
                #pragma unroll
                for (int i = 0; i < 8; ++i) {
                    const float4 p = c_tab.pzT[i * 6 + q];
                    z01 = fma2(lo64(p), xp[i], z01);
                    z23 = fma2(hi64(p), xp[i], z23);
                }
                const float4 zmq = c_tab.zm[q];
                float2 v01 = u2f(a01), v23 = u2f(a23);
                float2 s01 = u2f(z01), s23 = u2f(z23);
                v01.x = fmaf(zmq.x, sig_f(s01.x), v01.x);
                v01.y = fmaf(zmq.y, sig_f(s01.y), v01.y);
                v23.x = fmaf(zmq.z, sig_f(s23.x), v23.x);
                v23.y = fmaf(zmq.w, sig_f(s23.y), v23.y);
                a01 = f2u(v01.x, v01.y);
                a23 = f2u(v23.x, v23.y);
            }

            ulonglong2 st; st.x = a01; st.y = a23;
            *reinterpret_cast<ulonglong2*>(&sm[t * SROW + 4 * q]) = st;  // STS.128
        }

        const int next = tile + (int)gridDim.x;
        __syncthreads();                        // staging complete

        // Prefetch next tile's x now: LDG latency hides under readback + STG.
        if (next < nTiles) {
            const int row = next * RPB + t;
            #pragma unroll
            for (int i = 0; i < 8; ++i)
                xf[i] = (row < B) ? __ldcs(x + (size_t)i * (size_t)B + row) : 0.0f;
        }

        // Coalesced writeout of this tile.
        const unsigned baseF4 = (unsigned)tile * 1536u;
        #pragma unroll
        for (int k = 0; k < 6; ++k) {
            const unsigned g = (unsigned)(k * 256 + t);
            if (baseF4 + g < totF4) {
                float4 o = *reinterpret_cast<const float4*>(&sm[soff[k]]);
                __stcs(out4 + (baseF4 + g), o);
            }
        }

        if (next >= nTiles) break;
        tile = next;
        __syncthreads();                        // before staging is overwritten
    }
}

// ---------------------------------------------------------------------------
extern "C" void kernel_launch(void* const* d_in, const int* in_sizes, int n_in,
                              void* d_out, int out_size) {
    const float* x  = (const float*)d_in[0];
    const float* W  = (const float*)d_in[1];
    const float* P  = (const float*)d_in[2];
    const float* bv = (const float*)d_in[3];
    const float* bz = (const float*)d_in[4];
    const float* e  = (const float*)d_in[5];
    const float* ep = (const float*)d_in[6];
    const float* cx = (const float*)d_in[7];
    const float* cu = (const float*)d_in[8];
    const float* cU = (const float*)d_in[9];
    const float* v0 = (const float*)d_in[10];
    const float* X0 = (const float*)d_in[11];
    const float* U0 = (const float*)d_in[12];

    const int B      = in_sizes[0] / 8;
    const int nTiles = (B + RPB - 1) / RPB;
    const int grid   = (nTiles < GRID_MAIN) ? nTiles : GRID_MAIN;

    cb_prologue<<<1, 256>>>(W, P, bv, bz, e, ep, cx, cu, cU, v0, X0, U0);

    void* src = nullptr;
    cudaGetSymbolAddress(&src, g_tab);
    cudaMemcpyToSymbolAsync(c_tab, src, sizeof(CTabT), 0,
                            cudaMemcpyDeviceToDevice, 0);

    if (grid > 0)
        cb_main<<<grid, TPB>>>(x, (float*)d_out, B, nTiles);
}

// round 10
// speedup vs baseline: 1.3672x; 1.3672x over previous
#include <cuda_runtime.h>

typedef unsigned long long u64;

#define TPB  256
#define RPB  256                          // rows per tile = 1 per thread
#define SROW 28                           // word stride: 16B-aligned, STS.128 conflict-free
#define STAGE_W (RPB * SROW)              // 7168 words = 28.7KB -> 7 blocks/SM (smem-capped)

// Transposed coefficient tables (i-major) so one constant load covers 4 h-channels.
struct __align__(16) CTabT {
    float4 pdT[48];   // pdT[i*6+q] = 0.1 * P[4q..4q+3][i]
    float4 c0[6];
    float4 pzT[48];   // pe*sp(P) transposed
    float4 a1[6];
    float4 zm[6];     // -dt*v0 quads
    float  flag;
    float  pad[3];
};

__device__   CTabT g_tab;
__constant__ CTabT c_tab;

__device__ __forceinline__ float sp_f(float x) {
    return fmaxf(x, 0.0f) + __logf(1.0f + __expf(-fabsf(x)));
}
__device__ __forceinline__ float sig_f(float x) {
    return 1.0f / (1.0f + __expf(-x));
}
__device__ __forceinline__ u64 fma2(u64 a, u64 b, u64 c) {
    u64 d;
    asm("fma.rn.f32x2 %0, %1, %2, %3;" : "=l"(d) : "l"(a), "l"(b), "l"(c));
    return d;
}
__device__ __forceinline__ u64 f2u(float a, float b) {
    u64 v;
    asm("mov.b64 %0, {%1, %2};" : "=l"(v) : "f"(a), "f"(b));
    return v;
}
__device__ __forceinline__ float2 u2f(u64 v) {
    float2 r;
    asm("mov.b64 {%0, %1}, %2;" : "=f"(r.x), "=f"(r.y) : "l"(v));
    return r;
}
__device__ __forceinline__ u64 lo64(float4 v) { return f2u(v.x, v.y); }
__device__ __forceinline__ u64 hi64(float4 v) { return f2u(v.z, v.w); }

// ---------------------------------------------------------------------------
// Prologue kernel: one block computes all batch-invariant values -> g_tab.
// ---------------------------------------------------------------------------
__global__ void cb_prologue(const float* __restrict__ W,  const float* __restrict__ P,
                            const float* __restrict__ bv, const float* __restrict__ bz,
                            const float* __restrict__ e,  const float* __restrict__ ep,
                            const float* __restrict__ cx, const float* __restrict__ cu,
                            const float* __restrict__ cU, const float* __restrict__ v0,
                            const float* __restrict__ X0, const float* __restrict__ U0)
{
    __shared__ float rS[24], wS[24], pkr[192], pwr[192];
    const int t = threadIdx.x;

    if (t < 24) {
        float v0v = v0[t];
        float rv  = sig_f(v0v);
        rS[t] = rv;
        float zx = 0.001f + 0.099f * sig_f(cx[t]);
        float X  = zx + (1.0f - zx) * X0[t] - U0[t] * X0[t] * rv;   // delta_t=1
        float zu   = 0.001f + 0.099f * sig_f(cu[t]);
        float Ucap = 0.9f * sig_f(cU[t]);
        float U = Ucap * zu + (1.0f - zu) * U0[t] + Ucap * (1.0f - U0[t]) * rv;
        U = fminf(fmaxf(U, Ucap), 1.0f);
        wS[t] = U * X * rv;
        ((float*)g_tab.zm)[t] = -0.1f * v0v;
    }
    if (t == 0) {
        int f = 0;
        #pragma unroll
        for (int j = 0; j < 24; ++j) f |= (v0[j] != 0.0f);
        g_tab.flag = (float)f;
    }
    __syncthreads();

    if (t < 192) {
        const int h = t >> 3;                 // 0..23
        const int i = t & 7;                  // 0..7
        float kr = 0.0f, wur = 0.0f;
        #pragma unroll
        for (int jj = 0; jj < 3; ++jj) {
            int j = i * 3 + jj;
            float Wv = W[h * 24 + j];
            kr  += sp_f(Wv) * rS[j];
            wur += Wv * wS[j];
        }
        pkr[h * 8 + i] = kr;
        pwr[h * 8 + i] = wur;
        float pe = sp_f(ep[0]);
        float Pv = P[h * 8 + i];              // P is (H, IN) row-major
        ((float*)&g_tab.pdT[i * 6 + (h >> 2)])[h & 3] = 0.1f * Pv;
        ((float*)&g_tab.pzT[i * 6 + (h >> 2)])[h & 3] = pe * sp_f(Pv);
    }
    __syncthreads();

    if (t < 24) {
        float kr = 0.0f, wur = 0.0f;
        #pragma unroll
        for (int k = 0; k < 8; ++k) { kr += pkr[t * 8 + k]; wur += pwr[t * 8 + k]; }
        float ke = sp_f(e[0]);
        ((float*)g_tab.a1)[t] = ke * kr + bz[t];
        ((float*)g_tab.c0)[t] = v0[t] + 0.1f * (wur + bv[t]);
    }
}

// ---------------------------------------------------------------------------
// Main kernel: 1 row/thread, independent 256-row blocks (R8 structure).
// launch_bounds(256,6): 40 regs — smem caps blocks at 7 anyway, so don't
// strangle the register allocator for a residency it can't reach.
// ---------------------------------------------------------------------------
__global__ void __launch_bounds__(TPB, 6)
cb_main(const float* __restrict__ x, float* __restrict__ out, int B)
{
    __shared__ float sm[STAGE_W];
    const int t = threadIdx.x;
    const int row = blockIdx.x * RPB + t;       // lane <-> consecutive batch row

    // x packed (x, x) once: both f32x2 lanes are h-channels of the same row.
    u64 xp[8];
    #pragma unroll
    for (int i = 0; i < 8; ++i) {
        float v = (row < B) ? __ldcs(x + (size_t)i * (size_t)B + row) : 0.0f;
        xp[i] = f2u(v, v);
    }

    const bool slow = (c_tab.flag != 0.0f);

    #pragma unroll
    for (int q = 0; q < 6; ++q) {               // h-quad 4q .. 4q+3
        const float4 c0q = c_tab.c0[q];
        u64 a01 = lo64(c0q);
        u64 a23 = hi64(c0q);
        #pragma unroll
        for (int i = 0; i < 8; ++i) {
            const float4 p = c_tab.pdT[i * 6 + q];
            a01 = fma2(lo64(p), xp[i], a01);
            a23 = fma2(hi64(p), xp[i], a23);
        }

        if (slow) {
            // General case (v0 != 0): v += sig(a1 + Pz@x) * (-0.1*v0[h]). Exact.
            const float4 a1q = c_tab.a1[q];
            u64 z01 = lo64(a1q);
            u64 z23 = hi64(a1q);
            #pragma unroll
            for (int i = 0; i < 8; ++i) {
                const float4 p = c_tab.pzT[i * 6 + q];
                z01 = fma2(lo64(p), xp[i], z01);
                z23 = fma2(hi64(p), xp[i], z23);
            }
            const float4 zmq = c_tab.zm[q];
            float2 v01 = u2f(a01), v23 = u2f(a23);
            float2 s01 = u2f(z01), s23 = u2f(z23);
            v01.x = fmaf(zmq.x, sig_f(s01.x), v01.x);
            v01.y = fmaf(zmq.y, sig_f(s01.y), v01.y);
            v23.x = fmaf(zmq.z, sig_f(s23.x), v23.x);
            v23.y = fmaf(zmq.w, sig_f(s23.y), v23.y);
            a01 = f2u(v01.x, v01.y);
            a23 = f2u(v23.x, v23.y);
        }

        // STS.128: (28t + 4q)*4B is 16B-aligned; stride-28 phases conflict-free.
        ulonglong2 st; st.x = a01; st.y = a23;
        *reinterpret_cast<ulonglong2*>(&sm[t * SROW + 4 * q]) = st;
    }
    __syncthreads();

    // Coalesced writeout: block owns float4 range [blockIdx*1536, +1536).
    const unsigned totF4  = (unsigned)B * 6u;
    const unsigned baseF4 = (unsigned)blockIdx.x * 1536u;
    float4* out4 = (float4*)out;

    if (baseF4 + 1536u <= totF4) {
        // Full tile (common case): no per-element bound checks.
        #pragma unroll
        for (int k = 0; k < 6; ++k) {
            unsigned g = (unsigned)(k * 256 + t);
            unsigned r = g / 6u;
            unsigned c = g - r * 6u;
            float4 o = *reinterpret_cast<const float4*>(&sm[r * SROW + 4u * c]);
            __stcs(out4 + (baseF4 + g), o);
        }
    } else {
        #pragma unroll
        for (int k = 0; k < 6; ++k) {
            unsigned g = (unsigned)(k * 256 + t);
            if (baseF4 + g < totF4) {
                unsigned r = g / 6u;
                unsigned c = g - r * 6u;
                float4 o = *reinterpret_cast<const float4*>(&sm[r * SROW + 4u * c]);
                __stcs(out4 + (baseF4 + g), o);
            }
        }
    }
}

// ---------------------------------------------------------------------------
extern "C" void kernel_launch(void* const* d_in, const int* in_sizes, int n_in,
                              void* d_out, int out_size) {
    const float* x  = (const float*)d_in[0];
    const float* W  = (const float*)d_in[1];
    const float* P  = (const float*)d_in[2];
    const float* bv = (const float*)d_in[3];
    const float* bz = (const float*)d_in[4];
    const float* e  = (const float*)d_in[5];
    const float* ep = (const float*)d_in[6];
    const float* cx = (const float*)d_in[7];
    const float* cu = (const float*)d_in[8];
    const float* cU = (const float*)d_in[9];
    const float* v0 = (const float*)d_in[10];
    const float* X0 = (const float*)d_in[11];
    const float* U0 = (const float*)d_in[12];

    const int B  = in_sizes[0] / 8;
    const int nb = (B + RPB - 1) / RPB;

    cb_prologue<<<1, 256>>>(W, P, bv, bz, e, ep, cx, cu, cU, v0, X0, U0);

    void* src = nullptr;
    cudaGetSymbolAddress(&src, g_tab);
    cudaMemcpyToSymbolAsync(c_tab, src, sizeof(CTabT), 0,
                            cudaMemcpyDeviceToDevice, 0);

    if (nb > 0)
        cb_main<<<nb, TPB>>>(x, (float*)d_out, B);
}

// round 11
// speedup vs baseline: 1.5183x; 1.1105x over previous
#include <cuda_runtime.h>

typedef unsigned long long u64;

#define TPB  128
#define RPB  128                          // rows per tile = 1 per thread
#define SROW 28                           // word stride: 16B-aligned, STS.128 conflict-free
#define STAGE_W (RPB * SROW)              // 3584 words = 14.3KB -> ~14 blocks/SM

// Transposed coefficient tables (i-major) so one constant load covers 4 h-channels.
struct __align__(16) CTabT {
    float4 pdT[48];   // pdT[i*6+q] = 0.1 * P[4q..4q+3][i]
    float4 c0[6];
    float4 pzT[48];   // pe*sp(P) transposed
    float4 a1[6];
    float4 zm[6];     // -dt*v0 quads
    float  flag;
    float  pad[3];
};

__device__   CTabT g_tab;
__constant__ CTabT c_tab;

__device__ __forceinline__ float sp_f(float x) {
    return fmaxf(x, 0.0f) + __logf(1.0f + __expf(-fabsf(x)));
}
__device__ __forceinline__ float sig_f(float x) {
    return 1.0f / (1.0f + __expf(-x));
}
__device__ __forceinline__ u64 fma2(u64 a, u64 b, u64 c) {
    u64 d;
    asm("fma.rn.f32x2 %0, %1, %2, %3;" : "=l"(d) : "l"(a), "l"(b), "l"(c));
    return d;
}
__device__ __forceinline__ u64 f2u(float a, float b) {
    u64 v;
    asm("mov.b64 %0, {%1, %2};" : "=l"(v) : "f"(a), "f"(b));
    return v;
}
__device__ __forceinline__ float2 u2f(u64 v) {
    float2 r;
    asm("mov.b64 {%0, %1}, %2;" : "=f"(r.x), "=f"(r.y) : "l"(v));
    return r;
}
__device__ __forceinline__ u64 lo64(float4 v) { return f2u(v.x, v.y); }
__device__ __forceinline__ u64 hi64(float4 v) { return f2u(v.z, v.w); }

// ---------------------------------------------------------------------------
// Prologue kernel: one block computes all batch-invariant values -> g_tab.
// ---------------------------------------------------------------------------
__global__ void cb_prologue(const float* __restrict__ W,  const float* __restrict__ P,
                            const float* __restrict__ bv, const float* __restrict__ bz,
                            const float* __restrict__ e,  const float* __restrict__ ep,
                            const float* __restrict__ cx, const float* __restrict__ cu,
                            const float* __restrict__ cU, const float* __restrict__ v0,
                            const float* __restrict__ X0, const float* __restrict__ U0)
{
    __shared__ float rS[24], wS[24], pkr[192], pwr[192];
    const int t = threadIdx.x;

    if (t < 24) {
        float v0v = v0[t];
        float rv  = sig_f(v0v);
        rS[t] = rv;
        float zx = 0.001f + 0.099f * sig_f(cx[t]);
        float X  = zx + (1.0f - zx) * X0[t] - U0[t] * X0[t] * rv;   // delta_t=1
        float zu   = 0.001f + 0.099f * sig_f(cu[t]);
        float Ucap = 0.9f * sig_f(cU[t]);
        float U = Ucap * zu + (1.0f - zu) * U0[t] + Ucap * (1.0f - U0[t]) * rv;
        U = fminf(fmaxf(U, Ucap), 1.0f);
        wS[t] = U * X * rv;
        ((float*)g_tab.zm)[t] = -0.1f * v0v;
    }
    if (t == 0) {
        int f = 0;
        #pragma unroll
        for (int j = 0; j < 24; ++j) f |= (v0[j] != 0.0f);
        g_tab.flag = (float)f;
    }
    __syncthreads();

    if (t < 192) {
        const int h = t >> 3;                 // 0..23
        const int i = t & 7;                  // 0..7
        float kr = 0.0f, wur = 0.0f;
        #pragma unroll
        for (int jj = 0; jj < 3; ++jj) {
            int j = i * 3 + jj;
            float Wv = W[h * 24 + j];
            kr  += sp_f(Wv) * rS[j];
            wur += Wv * wS[j];
        }
        pkr[h * 8 + i] = kr;
        pwr[h * 8 + i] = wur;
        float pe = sp_f(ep[0]);
        float Pv = P[h * 8 + i];              // P is (H, IN) row-major
        ((float*)&g_tab.pdT[i * 6 + (h >> 2)])[h & 3] = 0.1f * Pv;
        ((float*)&g_tab.pzT[i * 6 + (h >> 2)])[h & 3] = pe * sp_f(Pv);
    }
    __syncthreads();

    if (t < 24) {
        float kr = 0.0f, wur = 0.0f;
        #pragma unroll
        for (int k = 0; k < 8; ++k) { kr += pkr[t * 8 + k]; wur += pwr[t * 8 + k]; }
        float ke = sp_f(e[0]);
        ((float*)g_tab.a1)[t] = ke * kr + bz[t];
        ((float*)g_tab.c0)[t] = v0[t] + 0.1f * (wur + bv[t]);
    }
}

// ---------------------------------------------------------------------------
// Main kernel: 1 row/thread, independent 128-row blocks (R8 core, finer
// block granularity: ~14 blocks/SM, narrower barrier convoys).
// ---------------------------------------------------------------------------
__global__ void __launch_bounds__(TPB, 14)
cb_main(const float* __restrict__ x, float* __restrict__ out, int B)
{
    __shared__ float sm[STAGE_W];
    const int t = threadIdx.x;
    const int row = blockIdx.x * RPB + t;       // lane <-> consecutive batch row

    // x packed (x, x) once: both f32x2 lanes are h-channels of the same row.
    u64 xp[8];
    #pragma unroll
    for (int i = 0; i < 8; ++i) {
        float v = (row < B) ? __ldcs(x + (size_t)i * (size_t)B + row) : 0.0f;
        xp[i] = f2u(v, v);
    }

    const bool slow = (c_tab.flag != 0.0f);

    #pragma unroll
    for (int q = 0; q < 6; ++q) {               // h-quad 4q .. 4q+3
        const float4 c0q = c_tab.c0[q];
        u64 a01 = lo64(c0q);
        u64 a23 = hi64(c0q);
        #pragma unroll
        for (int i = 0; i < 8; ++i) {
            const float4 p = c_tab.pdT[i * 6 + q];
            a01 = fma2(lo64(p), xp[i], a01);
            a23 = fma2(hi64(p), xp[i], a23);
        }

        if (slow) {
            // General case (v0 != 0): v += sig(a1 + Pz@x) * (-0.1*v0[h]). Exact.
            const float4 a1q = c_tab.a1[q];
            u64 z01 = lo64(a1q);
            u64 z23 = hi64(a1q);
            #pragma unroll
            for (int i = 0; i < 8; ++i) {
                const float4 p = c_tab.pzT[i * 6 + q];
                z01 = fma2(lo64(p), xp[i], z01);
                z23 = fma2(hi64(p), xp[i], z23);
            }
            const float4 zmq = c_tab.zm[q];
            float2 v01 = u2f(a01), v23 = u2f(a23);
            float2 s01 = u2f(z01), s23 = u2f(z23);
            v01.x = fmaf(zmq.x, sig_f(s01.x), v01.x);
            v01.y = fmaf(zmq.y, sig_f(s01.y), v01.y);
            v23.x = fmaf(zmq.z, sig_f(s23.x), v23.x);
            v23.y = fmaf(zmq.w, sig_f(s23.y), v23.y);
            a01 = f2u(v01.x, v01.y);
            a23 = f2u(v23.x, v23.y);
        }

        // STS.128: (28t + 4q)*4B is 16B-aligned; stride-28 phases conflict-free.
        ulonglong2 st; st.x = a01; st.y = a23;
        *reinterpret_cast<ulonglong2*>(&sm[t * SROW + 4 * q]) = st;
    }
    __syncthreads();

    // Coalesced writeout: block owns float4 range [blockIdx*768, +768).
    const unsigned totF4  = (unsigned)B * 6u;
    const unsigned baseF4 = (unsigned)blockIdx.x * 768u;
    float4* out4 = (float4*)out;

    if (baseF4 + 768u <= totF4) {
        // Full tile (common case): no per-element bound checks.
        #pragma unroll
        for (int k = 0; k < 6; ++k) {
            unsigned g = (unsigned)(k * TPB + t);
            unsigned r = g / 6u;
            unsigned c = g - r * 6u;
            float4 o = *reinterpret_cast<const float4*>(&sm[r * SROW + 4u * c]);
            __stcs(out4 + (baseF4 + g), o);
        }
    } else {
        #pragma unroll
        for (int k = 0; k < 6; ++k) {
            unsigned g = (unsigned)(k * TPB + t);
            if (baseF4 + g < totF4) {
                unsigned r = g / 6u;
                unsigned c = g - r * 6u;
                float4 o = *reinterpret_cast<const float4*>(&sm[r * SROW + 4u * c]);
                __stcs(out4 + (baseF4 + g), o);
            }
        }
    }
}

// ---------------------------------------------------------------------------
extern "C" void kernel_launch(void* const* d_in, const int* in_sizes, int n_in,
                              void* d_out, int out_size) {
    const float* x  = (const float*)d_in[0];
    const float* W  = (const float*)d_in[1];
    const float* P  = (const float*)d_in[2];
    const float* bv = (const float*)d_in[3];
    const float* bz = (const float*)d_in[4];
    const float* e  = (const float*)d_in[5];
    const float* ep = (const float*)d_in[6];
    const float* cx = (const float*)d_in[7];
    const float* cu = (const float*)d_in[8];
    const float* cU = (const float*)d_in[9];
    const float* v0 = (const float*)d_in[10];
    const float* X0 = (const float*)d_in[11];
    const float* U0 = (const float*)d_in[12];

    const int B  = in_sizes[0] / 8;
    const int nb = (B + RPB - 1) / RPB;

    cb_prologue<<<1, 256>>>(W, P, bv, bz, e, ep, cx, cu, cU, v0, X0, U0);

    void* src = nullptr;
    cudaGetSymbolAddress(&src, g_tab);
    cudaMemcpyToSymbolAsync(c_tab, src, sizeof(CTabT), 0,
                            cudaMemcpyDeviceToDevice, 0);

    if (nb > 0)
        cb_main<<<nb, TPB>>>(x, (float*)d_out, B);
}

// round 12
// speedup vs baseline: 1.9169x; 1.2626x over previous
#include <cuda_runtime.h>

typedef unsigned long long u64;

#define TPB  256
#define RPB  256                          // rows per tile = 1 per thread
#define SROW 28                           // word stride: 16B-aligned, STS.128 conflict-free
#define STAGE_W (RPB * SROW)              // 7168 words = 28.7KB -> 7 blocks/SM

// Transposed coefficient tables (i-major) so one constant load covers 4 h-channels.
struct __align__(16) CTabT {
    float4 pdT[48];   // pdT[i*6+q] = 0.1 * P[4q..4q+3][i]
    float4 c0[6];
    float4 pzT[48];   // pe*sp(P) transposed
    float4 a1[6];
    float4 zm[6];     // -dt*v0 quads
    float  flag;
    float  pad[3];
};

__device__   CTabT g_tab;
__constant__ CTabT c_tab;

__device__ __forceinline__ float sp_f(float x) {
    return fmaxf(x, 0.0f) + __logf(1.0f + __expf(-fabsf(x)));
}
__device__ __forceinline__ float sig_f(float x) {
    return 1.0f / (1.0f + __expf(-x));
}
__device__ __forceinline__ u64 fma2(u64 a, u64 b, u64 c) {
    u64 d;
    asm("fma.rn.f32x2 %0, %1, %2, %3;" : "=l"(d) : "l"(a), "l"(b), "l"(c));
    return d;
}
__device__ __forceinline__ u64 f2u(float a, float b) {
    u64 v;
    asm("mov.b64 %0, {%1, %2};" : "=l"(v) : "f"(a), "f"(b));
    return v;
}
__device__ __forceinline__ float2 u2f(u64 v) {
    float2 r;
    asm("mov.b64 {%0, %1}, %2;" : "=f"(r.x), "=f"(r.y) : "l"(v));
    return r;
}
__device__ __forceinline__ u64 lo64(float4 v) { return f2u(v.x, v.y); }
__device__ __forceinline__ u64 hi64(float4 v) { return f2u(v.z, v.w); }

// ---------------------------------------------------------------------------
// Prologue kernel: one block computes all batch-invariant values -> g_tab.
// ---------------------------------------------------------------------------
__global__ void cb_prologue(const float* __restrict__ W,  const float* __restrict__ P,
                            const float* __restrict__ bv, const float* __restrict__ bz,
                            const float* __restrict__ e,  const float* __restrict__ ep,
                            const float* __restrict__ cx, const float* __restrict__ cu,
                            const float* __restrict__ cU, const float* __restrict__ v0,
                            const float* __restrict__ X0, const float* __restrict__ U0)
{
    __shared__ float rS[24], wS[24], pkr[192], pwr[192];
    const int t = threadIdx.x;

    if (t < 24) {
        float v0v = v0[t];
        float rv  = sig_f(v0v);
        rS[t] = rv;
        float zx = 0.001f + 0.099f * sig_f(cx[t]);
        float X  = zx + (1.0f - zx) * X0[t] - U0[t] * X0[t] * rv;   // delta_t=1
        float zu   = 0.001f + 0.099f * sig_f(cu[t]);
        float Ucap = 0.9f * sig_f(cU[t]);
        float U = Ucap * zu + (1.0f - zu) * U0[t] + Ucap * (1.0f - U0[t]) * rv;
        U = fminf(fmaxf(U, Ucap), 1.0f);
        wS[t] = U * X * rv;
        ((float*)g_tab.zm)[t] = -0.1f * v0v;
    }
    if (t == 0) {
        int f = 0;
        #pragma unroll
        for (int j = 0; j < 24; ++j) f |= (v0[j] != 0.0f);
        g_tab.flag = (float)f;
    }
    __syncthreads();

    if (t < 192) {
        const int h = t >> 3;                 // 0..23
        const int i = t & 7;                  // 0..7
        float kr = 0.0f, wur = 0.0f;
        #pragma unroll
        for (int jj = 0; jj < 3; ++jj) {
            int j = i * 3 + jj;
            float Wv = W[h * 24 + j];
            kr  += sp_f(Wv) * rS[j];
            wur += Wv * wS[j];
        }
        pkr[h * 8 + i] = kr;
        pwr[h * 8 + i] = wur;
        float pe = sp_f(ep[0]);
        float Pv = P[h * 8 + i];              // P is (H, IN) row-major
        ((float*)&g_tab.pdT[i * 6 + (h >> 2)])[h & 3] = 0.1f * Pv;
        ((float*)&g_tab.pzT[i * 6 + (h >> 2)])[h & 3] = pe * sp_f(Pv);
    }
    __syncthreads();

    if (t < 24) {
        float kr = 0.0f, wur = 0.0f;
        #pragma unroll
        for (int k = 0; k < 8; ++k) { kr += pkr[t * 8 + k]; wur += pwr[t * 8 + k]; }
        float ke = sp_f(e[0]);
        ((float*)g_tab.a1)[t] = ke * kr + bz[t];
        ((float*)g_tab.c0)[t] = v0[t] + 0.1f * (wur + bv[t]);
    }
}

// ---------------------------------------------------------------------------
// Main kernel: 1 row/thread, R8 core. Staging and writeout are WARP-LOCAL:
// no block barrier — each warp stages its own 32 rows and writes them out.
// ---------------------------------------------------------------------------
__global__ void __launch_bounds__(TPB, 7)
cb_main(const float* __restrict__ x, float* __restrict__ out, int B)
{
    __shared__ float sm[STAGE_W];
    const int t    = threadIdx.x;
    const int lane = t & 31;
    const int w    = t >> 5;                    // warp id in block
    const int row  = blockIdx.x * RPB + t;      // lane <-> consecutive batch row

    // x packed (x, x) once: both f32x2 lanes are h-channels of the same row.
    u64 xp[8];
    #pragma unroll
    for (int i = 0; i < 8; ++i) {
        float v = (row < B) ? __ldcs(x + (size_t)i * (size_t)B + row) : 0.0f;
        xp[i] = f2u(v, v);
    }

    const bool slow = (c_tab.flag != 0.0f);

    #pragma unroll
    for (int q = 0; q < 6; ++q) {               // h-quad 4q .. 4q+3
        const float4 c0q = c_tab.c0[q];
        u64 a01 = lo64(c0q);
        u64 a23 = hi64(c0q);
        #pragma unroll
        for (int i = 0; i < 8; ++i) {
            const float4 p = c_tab.pdT[i * 6 + q];
            a01 = fma2(lo64(p), xp[i], a01);
            a23 = fma2(hi64(p), xp[i], a23);
        }

        if (slow) {
            // General case (v0 != 0): v += sig(a1 + Pz@x) * (-0.1*v0[h]). Exact.
            const float4 a1q = c_tab.a1[q];
            u64 z01 = lo64(a1q);
            u64 z23 = hi64(a1q);
            #pragma unroll
            for (int i = 0; i < 8; ++i) {
                const float4 p = c_tab.pzT[i * 6 + q];
                z01 = fma2(lo64(p), xp[i], z01);
                z23 = fma2(hi64(p), xp[i], z23);
            }
            const float4 zmq = c_tab.zm[q];
            float2 v01 = u2f(a01), v23 = u2f(a23);
            float2 s01 = u2f(z01), s23 = u2f(z23);
            v01.x = fmaf(zmq.x, sig_f(s01.x), v01.x);
            v01.y = fmaf(zmq.y, sig_f(s01.y), v01.y);
            v23.x = fmaf(zmq.z, sig_f(s23.x), v23.x);
            v23.y = fmaf(zmq.w, sig_f(s23.y), v23.y);
            a01 = f2u(v01.x, v01.y);
            a23 = f2u(v23.x, v23.y);
        }

        // STS.128: (28t + 4q)*4B is 16B-aligned; stride-28 phases conflict-free.
        ulonglong2 st; st.x = a01; st.y = a23;
        *reinterpret_cast<ulonglong2*>(&sm[t * SROW + 4 * q]) = st;
    }

    __syncwarp();                               // warp-local smem visibility only

    // Warp-local coalesced writeout: warp w owns float4 range
    // [blockIdx*1536 + w*192, +192): its own rows [32w, 32w+32).
    const unsigned totF4  = (unsigned)B * 6u;
    const unsigned baseF4 = (unsigned)blockIdx.x * 1536u + (unsigned)w * 192u;
    float4* out4 = (float4*)out;

    if (baseF4 + 192u <= totF4) {
        #pragma unroll
        for (int k = 0; k < 6; ++k) {
            unsigned g = (unsigned)(w * 192 + k * 32 + lane);   // block-local f4 idx
            unsigned r = g / 6u;                                // row in [32w, 32w+32)
            unsigned c = g - r * 6u;
            float4 o = *reinterpret_cast<const float4*>(&sm[r * SROW + 4u * c]);
            __stcs(out4 + ((unsigned)blockIdx.x * 1536u + g), o);
        }
    } else {
        #pragma unroll
        for (int k = 0; k < 6; ++k) {
            unsigned g = (unsigned)(w * 192 + k * 32 + lane);
            unsigned abs4 = (unsigned)blockIdx.x * 1536u + g;
            if (abs4 < totF4) {
                unsigned r = g / 6u;
                unsigned c = g - r * 6u;
                float4 o = *reinterpret_cast<const float4*>(&sm[r * SROW + 4u * c]);
                __stcs(out4 + abs4, o);
            }
        }
    }
}

// ---------------------------------------------------------------------------
extern "C" void kernel_launch(void* const* d_in, const int* in_sizes, int n_in,
                              void* d_out, int out_size) {
    const float* x  = (const float*)d_in[0];
    const float* W  = (const float*)d_in[1];
    const float* P  = (const float*)d_in[2];
    const float* bv = (const float*)d_in[3];
    const float* bz = (const float*)d_in[4];
    const float* e  = (const float*)d_in[5];
    const float* ep = (const float*)d_in[6];
    const float* cx = (const float*)d_in[7];
    const float* cu = (const float*)d_in[8];
    const float* cU = (const float*)d_in[9];
    const float* v0 = (const float*)d_in[10];
    const float* X0 = (const float*)d_in[11];
    const float* U0 = (const float*)d_in[12];

    const int B  = in_sizes[0] / 8;
    const int nb = (B + RPB - 1) / RPB;

    cb_prologue<<<1, 256>>>(W, P, bv, bz, e, ep, cx, cu, cU, v0, X0, U0);

    void* src = nullptr;
    cudaGetSymbolAddress(&src, g_tab);
    cudaMemcpyToSymbolAsync(c_tab, src, sizeof(CTabT), 0,
                            cudaMemcpyDeviceToDevice, 0);

    if (nb > 0)
        cb_main<<<nb, TPB>>>(x, (float*)d_out, B);
}